// round 13
// baseline (speedup 1.0000x reference)
#include <cuda_runtime.h>
#include <cuda_fp16.h>
#include <math.h>
#include <stdint.h>

// ---------------------------------------------------------------------------
// Problem constants: B=16, NC=512, H=W=32 (HW=1024), NH=8, DH=64, NG=4,
// CG=128, Hs=Ws=16 (ns=256), STRIDE=2, ORF=2, LN_EPS=1e-5
// ---------------------------------------------------------------------------

__device__ __forceinline__ uint32_t smem_u32(const void* p) {
    uint32_t a;
    asm("{ .reg .u64 t; cvta.to.shared.u64 t, %1; cvt.u32.u64 %0, t; }"
        : "=r"(a) : "l"(p));
    return a;
}
__device__ __forceinline__ void cpasync16(uint32_t dst, const void* src) {
    asm volatile("cp.async.cg.shared.global [%0], [%1], 16;" :: "r"(dst), "l"(src));
}
#define CP_COMMIT() asm volatile("cp.async.commit_group;" ::: "memory")
#define CP_WAIT0()  asm volatile("cp.async.wait_group 0;" ::: "memory")

__device__ __forceinline__ void mma_f16(float* c, const uint32_t* a, const uint32_t* b) {
    asm volatile(
        "mma.sync.aligned.m16n8k16.row.col.f32.f16.f16.f32 "
        "{%0,%1,%2,%3}, {%4,%5,%6,%7}, {%8,%9}, {%0,%1,%2,%3};"
        : "+f"(c[0]), "+f"(c[1]), "+f"(c[2]), "+f"(c[3])
        : "r"(a[0]), "r"(a[1]), "r"(a[2]), "r"(a[3]), "r"(b[0]), "r"(b[1]));
}
__device__ __forceinline__ void ldsm_x4(uint32_t a, uint32_t* r) {
    asm volatile("ldmatrix.sync.aligned.m8n8.x4.shared.b16 {%0,%1,%2,%3}, [%4];"
                 : "=r"(r[0]), "=r"(r[1]), "=r"(r[2]), "=r"(r[3]) : "r"(a));
}

// ---------------------------------------------------------------------------
// Device scratch
// ---------------------------------------------------------------------------
__device__ __half g_qTh [16 * 1024 * 512];   // q^T fp16, [b][hw][c]
__device__ __half g_xTh [16 * 1024 * 512];   // x^T fp16, [b][hw][c]
__device__ __half g_xsh [16 * 256 * 512];    // sampled x fp16, [b][s][c]
__device__ __half g_kh  [16 * 512 * 256];    // k fp16, [bh][d][s]
__device__ __half g_vh  [16 * 512 * 256];    // v fp16
__device__ __half g_outTh[16 * 1024 * 512];  // attention out fp16, [b][m][c]
__device__ float  g_pos [16 * 4 * 256 * 2];
__device__ __half g_Wh  [4 * 512 * 512];     // Wq,Wk,Wv,Wo fp16

// ---------------------------------------------------------------------------
// Prep: x transpose + weight cvt, one launch.
// ---------------------------------------------------------------------------
__global__ __launch_bounds__(256)
void prep_kernel(const float* __restrict__ x, __half* __restrict__ xTh,
                 const float* __restrict__ Wq, const float* __restrict__ Wk,
                 const float* __restrict__ Wv, const float* __restrict__ Wo,
                 __half* __restrict__ Wh)
{
    if (blockIdx.x < 8192) {
        __shared__ float t[32][33];
        const int bid = blockIdx.x;
        const int b = bid >> 9;
        const int rem = bid & 511;
        const int hw0 = (rem & 31) * 32, c0 = (rem >> 5) * 32;
        const int tx = threadIdx.x & 31, ty = threadIdx.x >> 5;
        const float* xb = x + (size_t)b * 512 * 1024;
        __half* xTb = xTh + (size_t)b * 1024 * 512;
#pragma unroll
        for (int j = 0; j < 4; j++)
            t[ty + j * 8][tx] = xb[(size_t)(c0 + ty + j * 8) * 1024 + hw0 + tx];
        __syncthreads();
#pragma unroll
        for (int j = 0; j < 4; j++)
            xTb[(size_t)(hw0 + ty + j * 8) * 512 + c0 + tx] =
                __float2half(t[tx][ty + j * 8]);
    } else {
        const int cid = blockIdx.x - 8192;
        const int w = cid >> 10;
        const int i = (cid & 1023) * 256 + threadIdx.x;
        const float* src = (w == 0) ? Wq : (w == 1) ? Wk : (w == 2) ? Wv : Wo;
        Wh[(size_t)w * 262144 + i] = __float2half(src[i]);
    }
}

// ---------------------------------------------------------------------------
// cp.async-pipelined fp16 GEMM. Tile 128x128, chunk k64, 256 threads
// (8 warps 2m x 4n), 2 smem stages, one barrier per chunk (wait0 pattern).
// smem rows 144 B (64 halves + pad); word-stride 36 == 4 mod 32: conflict-free.
// ---------------------------------------------------------------------------
#define HROW 144
#define HSTG_A (128 * HROW)
#define HSTG   (2 * HSTG_A)          // 36864 B per stage
#define GSM_BYTES (2 * HSTG)         // 73728 B

template <int BIASN, int OUTH>
__device__ __forceinline__ void gemm_body(
    const __half* __restrict__ Am, const __half* __restrict__ Bm,
    const float* __restrict__ bias, void* __restrict__ Ybv,
    int N, int bm, int bn, char* sm)
{
    const int tid = threadIdx.x, lane = tid & 31, wid = tid >> 5;
    const int rg = lane >> 2, cl = lane & 3;
    const int wm = (wid >> 2) * 64, wn = (wid & 3) * 32;
    const uint32_t sb = smem_u32(sm);

    const int grp = lane >> 3, rr8 = lane & 7;
    const int arow = rr8 + (grp & 1) * 8;
    const uint32_t akb = (uint32_t)(grp >> 1) * 16;
    const int brow = (grp >> 1) * 8 + rr8;
    const uint32_t bkb = (uint32_t)(grp & 1) * 16;

    const int r = tid >> 1, hf = tid & 1;
    const __half* AgBase = Am + (size_t)(bm + r) * 512 + hf * 32;
    const __half* BgBase = Bm + (size_t)(bn + r) * 512 + hf * 32;
    const uint32_t doff = r * HROW + hf * 64;

    auto issue = [&](int stage, int k0) {     // k0 in halves
        uint32_t base = sb + stage * HSTG;
#pragma unroll
        for (int q = 0; q < 4; q++)
            cpasync16(base + doff + q * 16, AgBase + k0 + q * 8);
        uint32_t bb = base + HSTG_A;
#pragma unroll
        for (int q = 0; q < 4; q++)
            cpasync16(bb + doff + q * 16, BgBase + k0 + q * 8);
        CP_COMMIT();
    };
    issue(0, 0);

    float acc[4][4][4];
#pragma unroll
    for (int i = 0; i < 4; i++)
#pragma unroll
        for (int j = 0; j < 4; j++)
#pragma unroll
            for (int rr = 0; rr < 4; rr++) acc[i][j][rr] = 0.f;

    for (int cidx = 0; cidx < 8; cidx++) {
        CP_WAIT0();
        __syncthreads();
        if (cidx + 1 < 8) issue((cidx + 1) & 1, (cidx + 1) * 64);

        const uint32_t sbase = sb + (cidx & 1) * HSTG;

#pragma unroll
        for (int ks = 0; ks < 4; ks++) {
            uint32_t af[4][4], bf[4][2];
#pragma unroll
            for (int i = 0; i < 4; i++)
                ldsm_x4(sbase + (wm + i * 16 + arow) * HROW + ks * 32 + akb, af[i]);
#pragma unroll
            for (int jp = 0; jp < 2; jp++) {
                uint32_t r4[4];
                ldsm_x4(sbase + HSTG_A + (wn + jp * 16 + brow) * HROW + ks * 32 + bkb, r4);
                bf[jp * 2][0] = r4[0]; bf[jp * 2][1] = r4[1];
                bf[jp * 2 + 1][0] = r4[2]; bf[jp * 2 + 1][1] = r4[3];
            }
#pragma unroll
            for (int i = 0; i < 4; i++)
#pragma unroll
                for (int j = 0; j < 4; j++)
                    mma_f16(acc[i][j], af[i], bf[j]);
        }
    }
    __syncthreads();

#pragma unroll
    for (int i = 0; i < 4; i++) {
        int m = bm + wm + i * 16 + rg;
        float b0 = 0.f, b1 = 0.f;
        if (!BIASN) { b0 = bias[m]; b1 = bias[m + 8]; }
#pragma unroll
        for (int j = 0; j < 4; j++) {
            float v00, v01, v10, v11;
            if (BIASN) {
                b0 = bias[bn + wn + 2 * cl + j * 8];
                b1 = bias[bn + wn + 2 * cl + j * 8 + 1];
                v00 = acc[i][j][0] + b0; v01 = acc[i][j][1] + b1;
                v10 = acc[i][j][2] + b0; v11 = acc[i][j][3] + b1;
            } else {
                v00 = acc[i][j][0] + b0; v01 = acc[i][j][1] + b0;
                v10 = acc[i][j][2] + b1; v11 = acc[i][j][3] + b1;
            }
            if (OUTH) {
                __half* Yb = (__half*)Ybv;
                __half* y0 = Yb + (size_t)m * N + bn + wn + 2 * cl + j * 8;
                __half* y1 = y0 + (size_t)8 * N;
                *(__half2*)y0 = __floats2half2_rn(v00, v01);
                *(__half2*)y1 = __floats2half2_rn(v10, v11);
            } else {
                float* Yb = (float*)Ybv;
                float* y0 = Yb + (size_t)m * N + bn + wn + 2 * cl + j * 8;
                float* y1 = y0 + (size_t)8 * N;
                *(float2*)y0 = make_float2(v00, v01);
                *(float2*)y1 = make_float2(v10, v11);
            }
        }
    }
}

__global__ __launch_bounds__(256, 2)
void gemm_mma(const __half* __restrict__ Wh, const __half* __restrict__ XT,
              const float* __restrict__ bias, float* __restrict__ Y, int N)
{
    extern __shared__ char gsm[];
    const int b = blockIdx.z;
    gemm_body<0, 0>(Wh, XT + (size_t)b * N * 512, bias, Y + (size_t)b * 512 * N,
                    N, blockIdx.y * 128, blockIdx.x * 128, gsm);
}

__global__ __launch_bounds__(256, 2)
void gemm_mma_q(const __half* __restrict__ WhQ, const __half* __restrict__ xTh,
                const float* __restrict__ bq, __half* __restrict__ qTh)
{
    extern __shared__ char gsm[];
    const int b = blockIdx.z;
    gemm_body<1, 1>(xTh + (size_t)b * 524288, WhQ, bq, qTh + (size_t)b * 524288,
                    512, blockIdx.y * 128, blockIdx.x * 128, gsm);
}

__global__ __launch_bounds__(256, 2)
void gemm_mma_kv(const __half* __restrict__ Wh, const float* __restrict__ bk,
                 const float* __restrict__ bv, const __half* __restrict__ XTh,
                 __half* __restrict__ Yk, __half* __restrict__ Yv)
{
    extern __shared__ char gsm[];
    const int b = blockIdx.z;
    const int isv = blockIdx.y >> 2;
    gemm_body<0, 1>(Wh + (size_t)(1 + isv) * 262144, XTh + (size_t)b * 256 * 512,
                    isv ? bv : bk, (isv ? Yv : Yk) + (size_t)b * 512 * 256,
                    256, (blockIdx.y & 3) * 128, blockIdx.x * 128, gsm);
}

// ---------------------------------------------------------------------------
// Offset network, half2 channel pairs, 2 spatial positions per block.
// ---------------------------------------------------------------------------
__global__ __launch_bounds__(128)
void offset_kernel(const float* __restrict__ dw_w, const float* __restrict__ dw_b,
                   const float* __restrict__ ln_g, const float* __restrict__ ln_b,
                   const float* __restrict__ pw_w,
                   float* __restrict__ out_pos, float* __restrict__ out_ref)
{
    __shared__ float ra[4], rb[4], rc[4], rd[4];

    const int blk = blockIdx.x;          // 8192
    const int n = blk >> 7;
    const int sbase = (blk & 127) * 2;
    const int t = threadIdx.x;
    const int p = t >> 6;
    const int cp = t & 63;
    const int s = sbase + p;
    const int oy = s >> 4, ox = s & 15;
    const int bb = n >> 2, g = n & 3;
    const int lane = t & 31, warp = t >> 5;

    const __half2* qTb = (const __half2*)(g_qTh + (size_t)bb * 524288 + g * 128 + 2 * cp);

    float ax = dw_b[2 * cp], ay = dw_b[2 * cp + 1];
#pragma unroll
    for (int ky = 0; ky < 3; ky++) {
        int iy = oy * 2 - 1 + ky;
        if (iy < 0 || iy >= 32) continue;
#pragma unroll
        for (int kx = 0; kx < 3; kx++) {
            int ix = ox * 2 - 1 + kx;
            if (ix < 0 || ix >= 32) continue;
            float2 v = __half22float2(qTb[(size_t)(iy * 32 + ix) * 256]);
            ax += v.x * dw_w[(2 * cp) * 9 + ky * 3 + kx];
            ay += v.y * dw_w[(2 * cp + 1) * 9 + ky * 3 + kx];
        }
    }

    float s1 = ax + ay, s2 = ax * ax + ay * ay;
#pragma unroll
    for (int o = 16; o; o >>= 1) {
        s1 += __shfl_xor_sync(~0u, s1, o);
        s2 += __shfl_xor_sync(~0u, s2, o);
    }
    if (lane == 0) { ra[warp] = s1; rb[warp] = s2; }
    __syncthreads();
    float sum = ra[p * 2] + ra[p * 2 + 1];
    float sumsq = rb[p * 2] + rb[p * 2 + 1];
    float mean = sum * (1.f / 128.f);
    float var = sumsq * (1.f / 128.f) - mean * mean;
    float inv = rsqrtf(var + 1e-5f);
    float ox0 = (ax - mean) * inv * ln_g[2 * cp] + ln_b[2 * cp];
    float ox1 = (ay - mean) * inv * ln_g[2 * cp + 1] + ln_b[2 * cp + 1];
    ox0 = 0.5f * ox0 * (1.f + erff(ox0 * 0.70710678118654752f));
    ox1 = 0.5f * ox1 * (1.f + erff(ox1 * 0.70710678118654752f));

    float d0 = ox0 * pw_w[2 * cp] + ox1 * pw_w[2 * cp + 1];
    float d1 = ox0 * pw_w[128 + 2 * cp] + ox1 * pw_w[128 + 2 * cp + 1];
#pragma unroll
    for (int o = 16; o; o >>= 1) {
        d0 += __shfl_xor_sync(~0u, d0, o);
        d1 += __shfl_xor_sync(~0u, d1, o);
    }
    if (lane == 0) { rc[warp] = d0; rd[warp] = d1; }
    __syncthreads();

    if (cp == 0) {
        float vy = rc[p * 2] + rc[p * 2 + 1];
        float vx = rd[p * 2] + rd[p * 2 + 1];
        float offy = tanhf(vy) * (2.f / 15.f);
        float offx = tanhf(vx) * (2.f / 15.f);
        float refy = (0.5f + (float)oy) * (2.f / 15.f) - 1.f;
        float refx = (0.5f + (float)ox) * (2.f / 15.f) - 1.f;
        float py = offy + refy, px = offx + refx;
        int idx = (n * 256 + s) * 2;
        g_pos[idx] = py;  g_pos[idx + 1] = px;
        out_pos[idx] = py; out_pos[idx + 1] = px;
        out_ref[idx] = refy; out_ref[idx + 1] = refx;
    }
}

// ---------------------------------------------------------------------------
// Bilinear grid sample, half2 (2 channels per thread)
// ---------------------------------------------------------------------------
__global__ __launch_bounds__(256)
void sample_kernel(const __half* __restrict__ xTh)
{
    int idx = blockIdx.x * 256 + threadIdx.x;   // 16*256*256
    int chp = idx & 255;                         // channel pair
    int s   = (idx >> 8) & 255;
    int b   = idx >> 16;
    int g   = chp >> 6;

    int pidx = ((b * 4 + g) * 256 + s) * 2;
    float py = g_pos[pidx], px = g_pos[pidx + 1];
    float gx = (px + 1.f) * 15.5f;
    float gy = (py + 1.f) * 15.5f;

    const __half2* xb = (const __half2*)(xTh + (size_t)b * 524288) + chp;

    float fx0 = floorf(gx), fy0 = floorf(gy);
    int x0 = (int)fx0, y0 = (int)fy0;
    float wx1 = gx - fx0, wx0 = 1.f - wx1;
    float wy1 = gy - fy0, wy0 = 1.f - wy1;

    bool x0i = (x0 >= 0 && x0 < 32), x1i = (x0 >= -1 && x0 < 31);
    bool y0i = (y0 >= 0 && y0 < 32), y1i = (y0 >= -1 && y0 < 31);

    float2 z = make_float2(0.f, 0.f);
    float2 v00 = (y0i && x0i) ? __half22float2(xb[(size_t)(y0 * 32 + x0) * 256])           : z;
    float2 v01 = (y0i && x1i) ? __half22float2(xb[(size_t)(y0 * 32 + x0 + 1) * 256])       : z;
    float2 v10 = (y1i && x0i) ? __half22float2(xb[(size_t)((y0 + 1) * 32 + x0) * 256])     : z;
    float2 v11 = (y1i && x1i) ? __half22float2(xb[(size_t)((y0 + 1) * 32 + x0 + 1) * 256]) : z;

    float rx = wy0 * (wx0 * v00.x + wx1 * v01.x) + wy1 * (wx0 * v10.x + wx1 * v11.x);
    float ry = wy0 * (wx0 * v00.y + wx1 * v01.y) + wy1 * (wx0 * v10.y + wx1 * v11.y);
    ((__half2*)(g_xsh + (size_t)b * 131072 + s * 512))[chp] = __floats2half2_rn(rx, ry);
}

// ---------------------------------------------------------------------------
// Fused attention. 0.125 scale folded into K staging; Q staged via cp.async.
// 128 blocks, 512 threads (16 warps 4m x 4n), 128-query tiles.
// ---------------------------------------------------------------------------
#define KT_OFF 0
#define VT_OFF 36864
#define PQ_OFF 70656
#define F32_OFF 138240
#define ATTN_SMEM_BYTES (F32_OFF + 6020 * 4)

__global__ __launch_bounds__(512, 1)
void attn_mma(const float* __restrict__ rpe)
{
    extern __shared__ char smc[];
    __half* Kt  = (__half*)(smc + KT_OFF);
    __half* Vt  = (__half*)(smc + VT_OFF);
    float* tab   = (float*)(smc + F32_OFF);
    int*   xbase = (int*)(tab + 3972);
    float* wxf0  = (float*)(xbase + 256);
    float* wxf1  = wxf0 + 256;
    int*   ybase = (int*)(wxf1 + 256);
    float* wyf0  = (float*)(ybase + 256);
    float* wyf1  = wyf0 + 256;
    float* redS  = wyf1 + 256;

    const int bh = blockIdx.x;
    const int b = bh >> 3, h8 = bh & 7;
    const int g = h8 >> 1;
    const int tid = threadIdx.x;
    const int lane = tid & 31, wid = tid >> 5;
    const int rg = lane >> 2, c = lane & 3;
    const int wmw = (wid & 3) * 32;
    const int wn4 = wid >> 2;
    const int wn  = wn4 * 64;
    const int wd  = wn4 * 16;
    const int selw = wid & 3;
    const uint32_t sb = smem_u32(smc);

    const int grp = lane >> 3, rr8 = lane & 7;
    const int arow = rr8 + (grp & 1) * 8;
    const uint32_t akb = (uint32_t)(grp >> 1) * 16;
    const int brow = (grp >> 1) * 8 + rr8;
    const uint32_t bkb = (uint32_t)(grp & 1) * 16;

    const __half* kg = g_kh + (size_t)bh * 16384;
    const __half* vg = g_vh + (size_t)bh * 16384;
    const __half hs = __float2half(0.125f);
    for (int i = tid; i < 16384; i += 512) {
        int d = i >> 8, s = i & 255;
        Kt[s * 72 + d]  = __hmul(kg[i], hs);   // exact: power of 2
        Vt[d * 264 + s] = vg[i];
    }
    for (int i = tid; i < 3969; i += 512) tab[i] = rpe[h8 * 3969 + i];
    if (tid < 256) {
        int pidx = ((b * 4 + g) * 256 + tid) * 2;
        float by = 15.5f - 15.5f * g_pos[pidx];
        float bx = 15.5f - 15.5f * g_pos[pidx + 1];
        float fby = floorf(by), fbx = floorf(bx);
        ybase[tid] = (int)fby;
        wyf1[tid] = by - fby;
        wyf0[tid] = 1.f - (by - fby);
        xbase[tid] = (int)fbx;
        wxf1[tid] = bx - fbx;
        wxf0[tid] = 1.f - (bx - fbx);
    }
    __syncthreads();

    const __half* qgTh = g_qTh + (size_t)b * 524288 + h8 * 64;
    __half* outg = g_outTh + (size_t)b * 524288 + h8 * 64;

    int mxi[2][2];
#pragma unroll
    for (int i = 0; i < 2; i++)
#pragma unroll
        for (int r2 = 0; r2 < 2; r2++)
            mxi[i][r2] = (wmw + i * 16 + rg + r2 * 8) & 31;

    for (int m0 = 0; m0 < 1024; m0 += 128) {
        // ---- stage Q tile via cp.async (pure copy; scale lives in K) ----
#pragma unroll
        for (int rep = 0; rep < 2; rep++) {
            int pos = tid + rep * 512;          // 1024 x 16B segments
            int row = pos >> 3, seg = pos & 7;
            cpasync16(sb + PQ_OFF + row * 144 + seg * 16,
                      qgTh + (size_t)(m0 + row) * 512 + seg * 8);
        }
        CP_COMMIT();
        CP_WAIT0();
        __syncthreads();

        const int myt = (m0 >> 5) + selw;

        float sacc[2][8][4];
#pragma unroll
        for (int i = 0; i < 2; i++)
#pragma unroll
            for (int t = 0; t < 8; t++)
#pragma unroll
                for (int r = 0; r < 4; r++) sacc[i][t][r] = 0.f;

#pragma unroll
        for (int ks = 0; ks < 4; ks++) {
            uint32_t af[2][4], bf[8][2];
#pragma unroll
            for (int i = 0; i < 2; i++)
                ldsm_x4(sb + PQ_OFF + (wmw + i * 16 + arow) * 144 + ks * 32 + akb, af[i]);
#pragma unroll
            for (int tp = 0; tp < 4; tp++) {
                uint32_t r4[4];
                ldsm_x4(sb + KT_OFF + (wn + tp * 16 + brow) * 144 + ks * 32 + bkb, r4);
                bf[tp * 2][0] = r4[0]; bf[tp * 2][1] = r4[1];
                bf[tp * 2 + 1][0] = r4[2]; bf[tp * 2 + 1][1] = r4[3];
            }
#pragma unroll
            for (int t = 0; t < 8; t++) {
                mma_f16(sacc[0][t], af[0], bf[t]);
                mma_f16(sacc[1][t], af[1], bf[t]);
            }
        }

#pragma unroll
        for (int t = 0; t < 8; t++) {
#pragma unroll
            for (int cc = 0; cc < 2; cc++) {
                int n = wn + t * 8 + 2 * c + cc;
                int y0 = myt + ybase[n];
                float w0 = (y0 >= 0 && y0 < 63) ? wyf0[n] : 0.f;
                float w1 = (y0 >= -1 && y0 < 62) ? wyf1[n] : 0.f;
                int o0 = min(max(y0, 0), 62) * 63;
                int o1 = min(max(y0 + 1, 0), 62) * 63;
                int xb = xbase[n];
                float wx0n = wxf0[n], wx1n = wxf1[n];
#pragma unroll
                for (int i = 0; i < 2; i++) {
#pragma unroll
                    for (int r2 = 0; r2 < 2; r2++) {
                        int x0 = mxi[i][r2] + xb;
                        float u0 = (x0 >= 0 && x0 < 63) ? wx0n : 0.f;
                        float u1 = (x0 >= -1 && x0 < 62) ? wx1n : 0.f;
                        int x0c = min(max(x0, 0), 62);
                        int x1c = min(max(x0 + 1, 0), 62);
                        float bias = w0 * (u0 * tab[o0 + x0c] + u1 * tab[o0 + x1c])
                                   + w1 * (u0 * tab[o1 + x0c] + u1 * tab[o1 + x1c]);
                        sacc[i][t][r2 * 2 + cc] += bias;
                    }
                }
            }
        }
        __syncthreads();

#pragma unroll
        for (int i = 0; i < 2; i++) {
#pragma unroll
            for (int r2 = 0; r2 < 2; r2++) {
                int m_l = wmw + i * 16 + rg + r2 * 8;
                float sum = 0.f;
#pragma unroll
                for (int t = 0; t < 8; t++) {
                    float e0 = __expf(sacc[i][t][r2 * 2 + 0]);
                    float e1 = __expf(sacc[i][t][r2 * 2 + 1]);
                    sum += e0 + e1;
                    *(__half2*)(smc + PQ_OFF + m_l * 528 + (wn + t * 8 + 2 * c) * 2) =
                        __floats2half2_rn(e0, e1);
                }
                sum += __shfl_xor_sync(~0u, sum, 1);
                sum += __shfl_xor_sync(~0u, sum, 2);
                if (c == 0) redS[m_l * 4 + wn4] = sum;
            }
        }
        __syncthreads();

        float oacc[2][2][4];
#pragma unroll
        for (int i = 0; i < 2; i++)
#pragma unroll
            for (int j = 0; j < 2; j++)
#pragma unroll
                for (int r = 0; r < 4; r++) oacc[i][j][r] = 0.f;

#pragma unroll 4
        for (int ks = 0; ks < 16; ks++) {
            uint32_t af[2][4], bf[2][2];
#pragma unroll
            for (int i = 0; i < 2; i++)
                ldsm_x4(sb + PQ_OFF + (wmw + i * 16 + arow) * 528 + ks * 32 + akb, af[i]);
            {
                uint32_t r4[4];
                ldsm_x4(sb + VT_OFF + (wd + brow) * 528 + ks * 32 + bkb, r4);
                bf[0][0] = r4[0]; bf[0][1] = r4[1];
                bf[1][0] = r4[2]; bf[1][1] = r4[3];
            }
#pragma unroll
            for (int j = 0; j < 2; j++) {
                mma_f16(oacc[0][j], af[0], bf[j]);
                mma_f16(oacc[1][j], af[1], bf[j]);
            }
        }

#pragma unroll
        for (int i = 0; i < 2; i++) {
#pragma unroll
            for (int r2 = 0; r2 < 2; r2++) {
                int m_l = wmw + i * 16 + rg + r2 * 8;
                const float* rs = redS + m_l * 4;
                float inv = 1.f / (rs[0] + rs[1] + rs[2] + rs[3]);
                __half* orow = outg + (size_t)(m0 + m_l) * 512;
#pragma unroll
                for (int j = 0; j < 2; j++) {
                    float o0 = oacc[i][j][r2 * 2 + 0] * inv;
                    float o1 = oacc[i][j][r2 * 2 + 1] * inv;
                    *(__half2*)(orow + wd + j * 8 + 2 * c) = __floats2half2_rn(o0, o1);
                }
            }
        }
        __syncthreads();
    }
}

// ---------------------------------------------------------------------------
// Launch
// ---------------------------------------------------------------------------
extern "C" void kernel_launch(void* const* d_in, const int* in_sizes, int n_in,
                              void* d_out, int out_size)
{
    const float* x    = (const float*)d_in[0];
    const float* Wq   = (const float*)d_in[1];
    const float* bq   = (const float*)d_in[2];
    const float* Wk   = (const float*)d_in[3];
    const float* bk   = (const float*)d_in[4];
    const float* Wv   = (const float*)d_in[5];
    const float* bv   = (const float*)d_in[6];
    const float* Wo   = (const float*)d_in[7];
    const float* bo   = (const float*)d_in[8];
    const float* dw_w = (const float*)d_in[9];
    const float* dw_b = (const float*)d_in[10];
    const float* ln_g = (const float*)d_in[11];
    const float* ln_b = (const float*)d_in[12];
    const float* pw_w = (const float*)d_in[13];
    const float* rpe  = (const float*)d_in[14];

    float* out     = (float*)d_out;
    float* y_out   = out;
    float* pos_out = out + 8388608;
    float* ref_out = out + 8388608 + 32768;

    void *p_qTh, *p_xTh, *p_xsh, *p_kh, *p_vh, *p_outTh, *p_Wh;
    cudaGetSymbolAddress(&p_qTh,   g_qTh);
    cudaGetSymbolAddress(&p_xTh,   g_xTh);
    cudaGetSymbolAddress(&p_xsh,   g_xsh);
    cudaGetSymbolAddress(&p_kh,    g_kh);
    cudaGetSymbolAddress(&p_vh,    g_vh);
    cudaGetSymbolAddress(&p_outTh, g_outTh);
    cudaGetSymbolAddress(&p_Wh,    g_Wh);

    cudaFuncSetAttribute(gemm_mma,    cudaFuncAttributeMaxDynamicSharedMemorySize, GSM_BYTES);
    cudaFuncSetAttribute(gemm_mma_q,  cudaFuncAttributeMaxDynamicSharedMemorySize, GSM_BYTES);
    cudaFuncSetAttribute(gemm_mma_kv, cudaFuncAttributeMaxDynamicSharedMemorySize, GSM_BYTES);
    cudaFuncSetAttribute(attn_mma,    cudaFuncAttributeMaxDynamicSharedMemorySize, ATTN_SMEM_BYTES);

    const __half* Wh = (const __half*)p_Wh;

    prep_kernel<<<12288, 256>>>(x, (__half*)p_xTh, Wq, Wk, Wv, Wo, (__half*)p_Wh);
    gemm_mma_q<<<dim3(4, 8, 16), 256, GSM_BYTES>>>(Wh, (const __half*)p_xTh, bq,
                                                   (__half*)p_qTh);
    offset_kernel<<<8192, 128>>>(dw_w, dw_b, ln_g, ln_b, pw_w, pos_out, ref_out);
    sample_kernel<<<4096, 256>>>((const __half*)p_xTh);
    gemm_mma_kv<<<dim3(2, 8, 16), 256, GSM_BYTES>>>(Wh, bk, bv, (const __half*)p_xsh,
                                                    (__half*)p_kh, (__half*)p_vh);
    attn_mma<<<128, 512, ATTN_SMEM_BYTES>>>(rpe);
    gemm_mma<<<dim3(8, 4, 16), 256, GSM_BYTES>>>(Wh + 3 * 262144, (const __half*)p_outTh,
                                                 bo, y_out, 1024);
}

// round 14
// speedup vs baseline: 1.0895x; 1.0895x over previous
#include <cuda_runtime.h>
#include <cuda_fp16.h>
#include <math.h>
#include <stdint.h>

// ---------------------------------------------------------------------------
// Problem constants: B=16, NC=512, H=W=32 (HW=1024), NH=8, DH=64, NG=4,
// CG=128, Hs=Ws=16 (ns=256), STRIDE=2, ORF=2, LN_EPS=1e-5
// ---------------------------------------------------------------------------

__device__ __forceinline__ uint32_t smem_u32(const void* p) {
    uint32_t a;
    asm("{ .reg .u64 t; cvta.to.shared.u64 t, %1; cvt.u32.u64 %0, t; }"
        : "=r"(a) : "l"(p));
    return a;
}
__device__ __forceinline__ void cpasync16(uint32_t dst, const void* src) {
    asm volatile("cp.async.cg.shared.global [%0], [%1], 16;" :: "r"(dst), "l"(src));
}
#define CP_COMMIT() asm volatile("cp.async.commit_group;" ::: "memory")
#define CP_WAIT1()  asm volatile("cp.async.wait_group 1;" ::: "memory")

__device__ __forceinline__ void mma_f16(float* c, const uint32_t* a, const uint32_t* b) {
    asm volatile(
        "mma.sync.aligned.m16n8k16.row.col.f32.f16.f16.f32 "
        "{%0,%1,%2,%3}, {%4,%5,%6,%7}, {%8,%9}, {%0,%1,%2,%3};"
        : "+f"(c[0]), "+f"(c[1]), "+f"(c[2]), "+f"(c[3])
        : "r"(a[0]), "r"(a[1]), "r"(a[2]), "r"(a[3]), "r"(b[0]), "r"(b[1]));
}
__device__ __forceinline__ void ldsm_x4(uint32_t a, uint32_t* r) {
    asm volatile("ldmatrix.sync.aligned.m8n8.x4.shared.b16 {%0,%1,%2,%3}, [%4];"
                 : "=r"(r[0]), "=r"(r[1]), "=r"(r[2]), "=r"(r[3]) : "r"(a));
}

// ---------------------------------------------------------------------------
// Device scratch
// ---------------------------------------------------------------------------
__device__ __half g_qTh [16 * 1024 * 512];   // q^T fp16, [b][hw][c]
__device__ __half g_xTh [16 * 1024 * 512];   // x^T fp16, [b][hw][c]
__device__ __half g_xsh [16 * 256 * 512];    // sampled x fp16, [b][s][c]
__device__ __half g_kh  [16 * 512 * 256];    // k fp16, [bh][d][s]
__device__ __half g_vh  [16 * 512 * 256];    // v fp16
__device__ __half g_outTh[16 * 1024 * 512];  // attention out fp16, [b][m][c]
__device__ float  g_pos [16 * 4 * 256 * 2];
__device__ __half g_Wh  [4 * 512 * 512];     // Wq,Wk,Wv,Wo fp16

// ---------------------------------------------------------------------------
// Prep: x transpose + weight cvt, one launch.
// ---------------------------------------------------------------------------
__global__ __launch_bounds__(256)
void prep_kernel(const float* __restrict__ x, __half* __restrict__ xTh,
                 const float* __restrict__ Wq, const float* __restrict__ Wk,
                 const float* __restrict__ Wv, const float* __restrict__ Wo,
                 __half* __restrict__ Wh)
{
    if (blockIdx.x < 8192) {
        __shared__ float t[32][33];
        const int bid = blockIdx.x;
        const int b = bid >> 9;
        const int rem = bid & 511;
        const int hw0 = (rem & 31) * 32, c0 = (rem >> 5) * 32;
        const int tx = threadIdx.x & 31, ty = threadIdx.x >> 5;
        const float* xb = x + (size_t)b * 512 * 1024;
        __half* xTb = xTh + (size_t)b * 1024 * 512;
#pragma unroll
        for (int j = 0; j < 4; j++)
            t[ty + j * 8][tx] = xb[(size_t)(c0 + ty + j * 8) * 1024 + hw0 + tx];
        __syncthreads();
#pragma unroll
        for (int j = 0; j < 4; j++)
            xTb[(size_t)(hw0 + ty + j * 8) * 512 + c0 + tx] =
                __float2half(t[tx][ty + j * 8]);
    } else {
        const int cid = blockIdx.x - 8192;
        const int w = cid >> 10;
        const int i = (cid & 1023) * 256 + threadIdx.x;
        const float* src = (w == 0) ? Wq : (w == 1) ? Wk : (w == 2) ? Wv : Wo;
        Wh[(size_t)w * 262144 + i] = __float2half(src[i]);
    }
}

// ---------------------------------------------------------------------------
// cp.async-pipelined fp16 GEMM (R12 configuration: k32 chunks, 3 stages,
// wait_group 1 — prefetch depth 2). 256 threads (8 warps 2m x 4n).
// ---------------------------------------------------------------------------
#define HROW 80
#define HSTG_A (128 * HROW)
#define HSTG   (2 * HSTG_A)
#define GSM_BYTES (3 * HSTG)

template <int BIASN, int OUTH>
__device__ __forceinline__ void gemm_body(
    const __half* __restrict__ Am, const __half* __restrict__ Bm,
    const float* __restrict__ bias, void* __restrict__ Ybv,
    int N, int bm, int bn, char* sm)
{
    const int tid = threadIdx.x, lane = tid & 31, wid = tid >> 5;
    const int rg = lane >> 2, cl = lane & 3;
    const int wm = (wid >> 2) * 64, wn = (wid & 3) * 32;
    const uint32_t sb = smem_u32(sm);

    const int grp = lane >> 3, rr8 = lane & 7;
    const int arow = rr8 + (grp & 1) * 8;
    const uint32_t akb = (uint32_t)(grp >> 1) * 16;
    const int brow = (grp >> 1) * 8 + rr8;
    const uint32_t bkb = (uint32_t)(grp & 1) * 16;

    const int r = tid >> 1, hf = tid & 1;
    const __half* AgBase = Am + (size_t)(bm + r) * 512 + hf * 16;
    const __half* BgBase = Bm + (size_t)(bn + r) * 512 + hf * 16;
    const uint32_t doff = r * HROW + hf * 32;

    auto issue = [&](int stage, int k0) {
        uint32_t base = sb + stage * HSTG;
        cpasync16(base + doff,      AgBase + k0);
        cpasync16(base + doff + 16, AgBase + k0 + 8);
        uint32_t bb = base + HSTG_A;
        cpasync16(bb + doff,      BgBase + k0);
        cpasync16(bb + doff + 16, BgBase + k0 + 8);
        CP_COMMIT();
    };
    issue(0, 0);
    issue(1, 32);

    float acc[4][4][4];
#pragma unroll
    for (int i = 0; i < 4; i++)
#pragma unroll
        for (int j = 0; j < 4; j++)
#pragma unroll
            for (int rr = 0; rr < 4; rr++) acc[i][j][rr] = 0.f;

    for (int cidx = 0; cidx < 16; cidx++) {
        CP_WAIT1();
        __syncthreads();
        if (cidx + 2 < 16) issue((cidx + 2) % 3, (cidx + 2) * 32);
        else CP_COMMIT();

        const uint32_t sbase = sb + (cidx % 3) * HSTG;

#pragma unroll
        for (int ks = 0; ks < 2; ks++) {
            uint32_t af[4][4], bf[4][2];
#pragma unroll
            for (int i = 0; i < 4; i++)
                ldsm_x4(sbase + (wm + i * 16 + arow) * HROW + ks * 32 + akb, af[i]);
#pragma unroll
            for (int jp = 0; jp < 2; jp++) {
                uint32_t r4[4];
                ldsm_x4(sbase + HSTG_A + (wn + jp * 16 + brow) * HROW + ks * 32 + bkb, r4);
                bf[jp * 2][0] = r4[0]; bf[jp * 2][1] = r4[1];
                bf[jp * 2 + 1][0] = r4[2]; bf[jp * 2 + 1][1] = r4[3];
            }
#pragma unroll
            for (int i = 0; i < 4; i++)
#pragma unroll
                for (int j = 0; j < 4; j++)
                    mma_f16(acc[i][j], af[i], bf[j]);
        }
    }
    __syncthreads();

#pragma unroll
    for (int i = 0; i < 4; i++) {
        int m = bm + wm + i * 16 + rg;
        float b0 = 0.f, b1 = 0.f;
        if (!BIASN) { b0 = bias[m]; b1 = bias[m + 8]; }
#pragma unroll
        for (int j = 0; j < 4; j++) {
            float v00, v01, v10, v11;
            if (BIASN) {
                b0 = bias[bn + wn + 2 * cl + j * 8];
                b1 = bias[bn + wn + 2 * cl + j * 8 + 1];
                v00 = acc[i][j][0] + b0; v01 = acc[i][j][1] + b1;
                v10 = acc[i][j][2] + b0; v11 = acc[i][j][3] + b1;
            } else {
                v00 = acc[i][j][0] + b0; v01 = acc[i][j][1] + b0;
                v10 = acc[i][j][2] + b1; v11 = acc[i][j][3] + b1;
            }
            if (OUTH) {
                __half* Yb = (__half*)Ybv;
                __half* y0 = Yb + (size_t)m * N + bn + wn + 2 * cl + j * 8;
                __half* y1 = y0 + (size_t)8 * N;
                *(__half2*)y0 = __floats2half2_rn(v00, v01);
                *(__half2*)y1 = __floats2half2_rn(v10, v11);
            } else {
                float* Yb = (float*)Ybv;
                float* y0 = Yb + (size_t)m * N + bn + wn + 2 * cl + j * 8;
                float* y1 = y0 + (size_t)8 * N;
                *(float2*)y0 = make_float2(v00, v01);
                *(float2*)y1 = make_float2(v10, v11);
            }
        }
    }
}

__global__ __launch_bounds__(256, 2)
void gemm_mma(const __half* __restrict__ Wh, const __half* __restrict__ XT,
              const float* __restrict__ bias, float* __restrict__ Y, int N)
{
    extern __shared__ char gsm[];
    const int b = blockIdx.z;
    gemm_body<0, 0>(Wh, XT + (size_t)b * N * 512, bias, Y + (size_t)b * 512 * N,
                    N, blockIdx.y * 128, blockIdx.x * 128, gsm);
}

__global__ __launch_bounds__(256, 2)
void gemm_mma_q(const __half* __restrict__ WhQ, const __half* __restrict__ xTh,
                const float* __restrict__ bq, __half* __restrict__ qTh)
{
    extern __shared__ char gsm[];
    const int b = blockIdx.z;
    gemm_body<1, 1>(xTh + (size_t)b * 524288, WhQ, bq, qTh + (size_t)b * 524288,
                    512, blockIdx.y * 128, blockIdx.x * 128, gsm);
}

__global__ __launch_bounds__(256, 2)
void gemm_mma_kv(const __half* __restrict__ Wh, const float* __restrict__ bk,
                 const float* __restrict__ bv, const __half* __restrict__ XTh,
                 __half* __restrict__ Yk, __half* __restrict__ Yv)
{
    extern __shared__ char gsm[];
    const int b = blockIdx.z;
    const int isv = blockIdx.y >> 2;
    gemm_body<0, 1>(Wh + (size_t)(1 + isv) * 262144, XTh + (size_t)b * 256 * 512,
                    isv ? bv : bk, (isv ? Yv : Yk) + (size_t)b * 512 * 256,
                    256, (blockIdx.y & 3) * 128, blockIdx.x * 128, gsm);
}

// ---------------------------------------------------------------------------
// Offset network, half2 channel pairs, 2 spatial positions per block.
// ---------------------------------------------------------------------------
__global__ __launch_bounds__(128)
void offset_kernel(const float* __restrict__ dw_w, const float* __restrict__ dw_b,
                   const float* __restrict__ ln_g, const float* __restrict__ ln_b,
                   const float* __restrict__ pw_w,
                   float* __restrict__ out_pos, float* __restrict__ out_ref)
{
    __shared__ float ra[4], rb[4], rc[4], rd[4];

    const int blk = blockIdx.x;          // 8192
    const int n = blk >> 7;
    const int sbase = (blk & 127) * 2;
    const int t = threadIdx.x;
    const int p = t >> 6;
    const int cp = t & 63;
    const int s = sbase + p;
    const int oy = s >> 4, ox = s & 15;
    const int bb = n >> 2, g = n & 3;
    const int lane = t & 31, warp = t >> 5;

    const __half2* qTb = (const __half2*)(g_qTh + (size_t)bb * 524288 + g * 128 + 2 * cp);

    float ax = dw_b[2 * cp], ay = dw_b[2 * cp + 1];
#pragma unroll
    for (int ky = 0; ky < 3; ky++) {
        int iy = oy * 2 - 1 + ky;
        if (iy < 0 || iy >= 32) continue;
#pragma unroll
        for (int kx = 0; kx < 3; kx++) {
            int ix = ox * 2 - 1 + kx;
            if (ix < 0 || ix >= 32) continue;
            float2 v = __half22float2(qTb[(size_t)(iy * 32 + ix) * 256]);
            ax += v.x * dw_w[(2 * cp) * 9 + ky * 3 + kx];
            ay += v.y * dw_w[(2 * cp + 1) * 9 + ky * 3 + kx];
        }
    }

    float s1 = ax + ay, s2 = ax * ax + ay * ay;
#pragma unroll
    for (int o = 16; o; o >>= 1) {
        s1 += __shfl_xor_sync(~0u, s1, o);
        s2 += __shfl_xor_sync(~0u, s2, o);
    }
    if (lane == 0) { ra[warp] = s1; rb[warp] = s2; }
    __syncthreads();
    float sum = ra[p * 2] + ra[p * 2 + 1];
    float sumsq = rb[p * 2] + rb[p * 2 + 1];
    float mean = sum * (1.f / 128.f);
    float var = sumsq * (1.f / 128.f) - mean * mean;
    float inv = rsqrtf(var + 1e-5f);
    float ox0 = (ax - mean) * inv * ln_g[2 * cp] + ln_b[2 * cp];
    float ox1 = (ay - mean) * inv * ln_g[2 * cp + 1] + ln_b[2 * cp + 1];
    ox0 = 0.5f * ox0 * (1.f + erff(ox0 * 0.70710678118654752f));
    ox1 = 0.5f * ox1 * (1.f + erff(ox1 * 0.70710678118654752f));

    float d0 = ox0 * pw_w[2 * cp] + ox1 * pw_w[2 * cp + 1];
    float d1 = ox0 * pw_w[128 + 2 * cp] + ox1 * pw_w[128 + 2 * cp + 1];
#pragma unroll
    for (int o = 16; o; o >>= 1) {
        d0 += __shfl_xor_sync(~0u, d0, o);
        d1 += __shfl_xor_sync(~0u, d1, o);
    }
    if (lane == 0) { rc[warp] = d0; rd[warp] = d1; }
    __syncthreads();

    if (cp == 0) {
        float vy = rc[p * 2] + rc[p * 2 + 1];
        float vx = rd[p * 2] + rd[p * 2 + 1];
        float offy = tanhf(vy) * (2.f / 15.f);
        float offx = tanhf(vx) * (2.f / 15.f);
        float refy = (0.5f + (float)oy) * (2.f / 15.f) - 1.f;
        float refx = (0.5f + (float)ox) * (2.f / 15.f) - 1.f;
        float py = offy + refy, px = offx + refx;
        int idx = (n * 256 + s) * 2;
        g_pos[idx] = py;  g_pos[idx + 1] = px;
        out_pos[idx] = py; out_pos[idx + 1] = px;
        out_ref[idx] = refy; out_ref[idx + 1] = refx;
    }
}

// ---------------------------------------------------------------------------
// Bilinear grid sample, half2 (2 channels per thread)
// ---------------------------------------------------------------------------
__global__ __launch_bounds__(256)
void sample_kernel(const __half* __restrict__ xTh)
{
    int idx = blockIdx.x * 256 + threadIdx.x;   // 16*256*256
    int chp = idx & 255;
    int s   = (idx >> 8) & 255;
    int b   = idx >> 16;
    int g   = chp >> 6;

    int pidx = ((b * 4 + g) * 256 + s) * 2;
    float py = g_pos[pidx], px = g_pos[pidx + 1];
    float gx = (px + 1.f) * 15.5f;
    float gy = (py + 1.f) * 15.5f;

    const __half2* xb = (const __half2*)(xTh + (size_t)b * 524288) + chp;

    float fx0 = floorf(gx), fy0 = floorf(gy);
    int x0 = (int)fx0, y0 = (int)fy0;
    float wx1 = gx - fx0, wx0 = 1.f - wx1;
    float wy1 = gy - fy0, wy0 = 1.f - wy1;

    bool x0i = (x0 >= 0 && x0 < 32), x1i = (x0 >= -1 && x0 < 31);
    bool y0i = (y0 >= 0 && y0 < 32), y1i = (y0 >= -1 && y0 < 31);

    float2 z = make_float2(0.f, 0.f);
    float2 v00 = (y0i && x0i) ? __half22float2(xb[(size_t)(y0 * 32 + x0) * 256])           : z;
    float2 v01 = (y0i && x1i) ? __half22float2(xb[(size_t)(y0 * 32 + x0 + 1) * 256])       : z;
    float2 v10 = (y1i && x0i) ? __half22float2(xb[(size_t)((y0 + 1) * 32 + x0) * 256])     : z;
    float2 v11 = (y1i && x1i) ? __half22float2(xb[(size_t)((y0 + 1) * 32 + x0 + 1) * 256]) : z;

    float rx = wy0 * (wx0 * v00.x + wx1 * v01.x) + wy1 * (wx0 * v10.x + wx1 * v11.x);
    float ry = wy0 * (wx0 * v00.y + wx1 * v01.y) + wy1 * (wx0 * v10.y + wx1 * v11.y);
    ((__half2*)(g_xsh + (size_t)b * 131072 + s * 512))[chp] = __floats2half2_rn(rx, ry);
}

// ---------------------------------------------------------------------------
// Fused attention. Scale folded into K staging; plain half2 Q copy.
// 128 blocks, 512 threads (16 warps 4m x 4n), 128-query tiles.
// ---------------------------------------------------------------------------
#define KT_OFF 0
#define VT_OFF 36864
#define PQ_OFF 70656
#define F32_OFF 138240
#define ATTN_SMEM_BYTES (F32_OFF + 6020 * 4)

__global__ __launch_bounds__(512, 1)
void attn_mma(const float* __restrict__ rpe)
{
    extern __shared__ char smc[];
    __half* Kt  = (__half*)(smc + KT_OFF);
    __half* Vt  = (__half*)(smc + VT_OFF);
    __half* PQh = (__half*)(smc + PQ_OFF);
    float* tab   = (float*)(smc + F32_OFF);
    int*   xbase = (int*)(tab + 3972);
    float* wxf0  = (float*)(xbase + 256);
    float* wxf1  = wxf0 + 256;
    int*   ybase = (int*)(wxf1 + 256);
    float* wyf0  = (float*)(ybase + 256);
    float* wyf1  = wyf0 + 256;
    float* redS  = wyf1 + 256;

    const int bh = blockIdx.x;
    const int b = bh >> 3, h8 = bh & 7;
    const int g = h8 >> 1;
    const int tid = threadIdx.x;
    const int lane = tid & 31, wid = tid >> 5;
    const int rg = lane >> 2, c = lane & 3;
    const int wmw = (wid & 3) * 32;
    const int wn4 = wid >> 2;
    const int wn  = wn4 * 64;
    const int wd  = wn4 * 16;
    const int selw = wid & 3;
    const uint32_t sb = smem_u32(smc);

    const int grp = lane >> 3, rr8 = lane & 7;
    const int arow = rr8 + (grp & 1) * 8;
    const uint32_t akb = (uint32_t)(grp >> 1) * 16;
    const int brow = (grp >> 1) * 8 + rr8;
    const uint32_t bkb = (uint32_t)(grp & 1) * 16;

    const __half* kg = g_kh + (size_t)bh * 16384;
    const __half* vg = g_vh + (size_t)bh * 16384;
    const __half hs = __float2half(0.125f);
    for (int i = tid; i < 16384; i += 512) {
        int d = i >> 8, s = i & 255;
        Kt[s * 72 + d]  = __hmul(kg[i], hs);   // exact: power of 2
        Vt[d * 264 + s] = vg[i];
    }
    for (int i = tid; i < 3969; i += 512) tab[i] = rpe[h8 * 3969 + i];
    if (tid < 256) {
        int pidx = ((b * 4 + g) * 256 + tid) * 2;
        float by = 15.5f - 15.5f * g_pos[pidx];
        float bx = 15.5f - 15.5f * g_pos[pidx + 1];
        float fby = floorf(by), fbx = floorf(bx);
        ybase[tid] = (int)fby;
        wyf1[tid] = by - fby;
        wyf0[tid] = 1.f - (by - fby);
        xbase[tid] = (int)fbx;
        wxf1[tid] = bx - fbx;
        wxf0[tid] = 1.f - (bx - fbx);
    }
    __syncthreads();

    const __half* qgTh = g_qTh + (size_t)b * 524288 + h8 * 64;
    __half* outg = g_outTh + (size_t)b * 524288 + h8 * 64;

    int mxi[2][2];
#pragma unroll
    for (int i = 0; i < 2; i++)
#pragma unroll
        for (int r2 = 0; r2 < 2; r2++)
            mxi[i][r2] = (wmw + i * 16 + rg + r2 * 8) & 31;

    for (int m0 = 0; m0 < 1024; m0 += 128) {
        // ---- stage Q tile (plain half2 copy; scale lives in K) ----
        for (int i = tid; i < 4096; i += 512) {
            int m = i >> 5, d2 = (i & 31) * 2;
            *(__half2*)(PQh + m * 72 + d2) =
                *(const __half2*)(qgTh + (size_t)(m0 + m) * 512 + d2);
        }
        __syncthreads();

        const int myt = (m0 >> 5) + selw;

        float sacc[2][8][4];
#pragma unroll
        for (int i = 0; i < 2; i++)
#pragma unroll
            for (int t = 0; t < 8; t++)
#pragma unroll
                for (int r = 0; r < 4; r++) sacc[i][t][r] = 0.f;

#pragma unroll
        for (int ks = 0; ks < 4; ks++) {
            uint32_t af[2][4], bf[8][2];
#pragma unroll
            for (int i = 0; i < 2; i++)
                ldsm_x4(sb + PQ_OFF + (wmw + i * 16 + arow) * 144 + ks * 32 + akb, af[i]);
#pragma unroll
            for (int tp = 0; tp < 4; tp++) {
                uint32_t r4[4];
                ldsm_x4(sb + KT_OFF + (wn + tp * 16 + brow) * 144 + ks * 32 + bkb, r4);
                bf[tp * 2][0] = r4[0]; bf[tp * 2][1] = r4[1];
                bf[tp * 2 + 1][0] = r4[2]; bf[tp * 2 + 1][1] = r4[3];
            }
#pragma unroll
            for (int t = 0; t < 8; t++) {
                mma_f16(sacc[0][t], af[0], bf[t]);
                mma_f16(sacc[1][t], af[1], bf[t]);
            }
        }

#pragma unroll
        for (int t = 0; t < 8; t++) {
#pragma unroll
            for (int cc = 0; cc < 2; cc++) {
                int n = wn + t * 8 + 2 * c + cc;
                int y0 = myt + ybase[n];
                float w0 = (y0 >= 0 && y0 < 63) ? wyf0[n] : 0.f;
                float w1 = (y0 >= -1 && y0 < 62) ? wyf1[n] : 0.f;
                int o0 = min(max(y0, 0), 62) * 63;
                int o1 = min(max(y0 + 1, 0), 62) * 63;
                int xb = xbase[n];
                float wx0n = wxf0[n], wx1n = wxf1[n];
#pragma unroll
                for (int i = 0; i < 2; i++) {
#pragma unroll
                    for (int r2 = 0; r2 < 2; r2++) {
                        int x0 = mxi[i][r2] + xb;
                        float u0 = (x0 >= 0 && x0 < 63) ? wx0n : 0.f;
                        float u1 = (x0 >= -1 && x0 < 62) ? wx1n : 0.f;
                        int x0c = min(max(x0, 0), 62);
                        int x1c = min(max(x0 + 1, 0), 62);
                        float bias = w0 * (u0 * tab[o0 + x0c] + u1 * tab[o0 + x1c])
                                   + w1 * (u0 * tab[o1 + x0c] + u1 * tab[o1 + x1c]);
                        sacc[i][t][r2 * 2 + cc] += bias;
                    }
                }
            }
        }
        __syncthreads();

#pragma unroll
        for (int i = 0; i < 2; i++) {
#pragma unroll
            for (int r2 = 0; r2 < 2; r2++) {
                int m_l = wmw + i * 16 + rg + r2 * 8;
                float sum = 0.f;
#pragma unroll
                for (int t = 0; t < 8; t++) {
                    float e0 = __expf(sacc[i][t][r2 * 2 + 0]);
                    float e1 = __expf(sacc[i][t][r2 * 2 + 1]);
                    sum += e0 + e1;
                    *(__half2*)(smc + PQ_OFF + m_l * 528 + (wn + t * 8 + 2 * c) * 2) =
                        __floats2half2_rn(e0, e1);
                }
                sum += __shfl_xor_sync(~0u, sum, 1);
                sum += __shfl_xor_sync(~0u, sum, 2);
                if (c == 0) redS[m_l * 4 + wn4] = sum;
            }
        }
        __syncthreads();

        float oacc[2][2][4];
#pragma unroll
        for (int i = 0; i < 2; i++)
#pragma unroll
            for (int j = 0; j < 2; j++)
#pragma unroll
                for (int r = 0; r < 4; r++) oacc[i][j][r] = 0.f;

#pragma unroll 4
        for (int ks = 0; ks < 16; ks++) {
            uint32_t af[2][4], bf[2][2];
#pragma unroll
            for (int i = 0; i < 2; i++)
                ldsm_x4(sb + PQ_OFF + (wmw + i * 16 + arow) * 528 + ks * 32 + akb, af[i]);
            {
                uint32_t r4[4];
                ldsm_x4(sb + VT_OFF + (wd + brow) * 528 + ks * 32 + bkb, r4);
                bf[0][0] = r4[0]; bf[0][1] = r4[1];
                bf[1][0] = r4[2]; bf[1][1] = r4[3];
            }
#pragma unroll
            for (int j = 0; j < 2; j++) {
                mma_f16(oacc[0][j], af[0], bf[j]);
                mma_f16(oacc[1][j], af[1], bf[j]);
            }
        }

#pragma unroll
        for (int i = 0; i < 2; i++) {
#pragma unroll
            for (int r2 = 0; r2 < 2; r2++) {
                int m_l = wmw + i * 16 + rg + r2 * 8;
                const float* rs = redS + m_l * 4;
                float inv = 1.f / (rs[0] + rs[1] + rs[2] + rs[3]);
                __half* orow = outg + (size_t)(m0 + m_l) * 512;
#pragma unroll
                for (int j = 0; j < 2; j++) {
                    float o0 = oacc[i][j][r2 * 2 + 0] * inv;
                    float o1 = oacc[i][j][r2 * 2 + 1] * inv;
                    *(__half2*)(orow + wd + j * 8 + 2 * c) = __floats2half2_rn(o0, o1);
                }
            }
        }
        __syncthreads();
    }
}

// ---------------------------------------------------------------------------
// Launch
// ---------------------------------------------------------------------------
extern "C" void kernel_launch(void* const* d_in, const int* in_sizes, int n_in,
                              void* d_out, int out_size)
{
    const float* x    = (const float*)d_in[0];
    const float* Wq   = (const float*)d_in[1];
    const float* bq   = (const float*)d_in[2];
    const float* Wk   = (const float*)d_in[3];
    const float* bk   = (const float*)d_in[4];
    const float* Wv   = (const float*)d_in[5];
    const float* bv   = (const float*)d_in[6];
    const float* Wo   = (const float*)d_in[7];
    const float* bo   = (const float*)d_in[8];
    const float* dw_w = (const float*)d_in[9];
    const float* dw_b = (const float*)d_in[10];
    const float* ln_g = (const float*)d_in[11];
    const float* ln_b = (const float*)d_in[12];
    const float* pw_w = (const float*)d_in[13];
    const float* rpe  = (const float*)d_in[14];

    float* out     = (float*)d_out;
    float* y_out   = out;
    float* pos_out = out + 8388608;
    float* ref_out = out + 8388608 + 32768;

    void *p_qTh, *p_xTh, *p_xsh, *p_kh, *p_vh, *p_outTh, *p_Wh;
    cudaGetSymbolAddress(&p_qTh,   g_qTh);
    cudaGetSymbolAddress(&p_xTh,   g_xTh);
    cudaGetSymbolAddress(&p_xsh,   g_xsh);
    cudaGetSymbolAddress(&p_kh,    g_kh);
    cudaGetSymbolAddress(&p_vh,    g_vh);
    cudaGetSymbolAddress(&p_outTh, g_outTh);
    cudaGetSymbolAddress(&p_Wh,    g_Wh);

    cudaFuncSetAttribute(gemm_mma,    cudaFuncAttributeMaxDynamicSharedMemorySize, GSM_BYTES);
    cudaFuncSetAttribute(gemm_mma_q,  cudaFuncAttributeMaxDynamicSharedMemorySize, GSM_BYTES);
    cudaFuncSetAttribute(gemm_mma_kv, cudaFuncAttributeMaxDynamicSharedMemorySize, GSM_BYTES);
    cudaFuncSetAttribute(attn_mma,    cudaFuncAttributeMaxDynamicSharedMemorySize, ATTN_SMEM_BYTES);

    const __half* Wh = (const __half*)p_Wh;

    prep_kernel<<<12288, 256>>>(x, (__half*)p_xTh, Wq, Wk, Wv, Wo, (__half*)p_Wh);
    gemm_mma_q<<<dim3(4, 8, 16), 256, GSM_BYTES>>>(Wh, (const __half*)p_xTh, bq,
                                                   (__half*)p_qTh);
    offset_kernel<<<8192, 128>>>(dw_w, dw_b, ln_g, ln_b, pw_w, pos_out, ref_out);
    sample_kernel<<<4096, 256>>>((const __half*)p_xTh);
    gemm_mma_kv<<<dim3(2, 8, 16), 256, GSM_BYTES>>>(Wh, bk, bv, (const __half*)p_xsh,
                                                    (__half*)p_kh, (__half*)p_vh);
    attn_mma<<<128, 512, ATTN_SMEM_BYTES>>>(rpe);
    gemm_mma<<<dim3(8, 4, 16), 256, GSM_BYTES>>>(Wh + 3 * 262144, (const __half*)p_outTh,
                                                 bo, y_out, 1024);
}

// round 15
// speedup vs baseline: 1.1029x; 1.0123x over previous
#include <cuda_runtime.h>
#include <cuda_fp16.h>
#include <math.h>
#include <stdint.h>

// ---------------------------------------------------------------------------
// Problem constants: B=16, NC=512, H=W=32 (HW=1024), NH=8, DH=64, NG=4,
// CG=128, Hs=Ws=16 (ns=256), STRIDE=2, ORF=2, LN_EPS=1e-5
// ---------------------------------------------------------------------------

__device__ __forceinline__ uint32_t smem_u32(const void* p) {
    uint32_t a;
    asm("{ .reg .u64 t; cvta.to.shared.u64 t, %1; cvt.u32.u64 %0, t; }"
        : "=r"(a) : "l"(p));
    return a;
}
__device__ __forceinline__ void cpasync16(uint32_t dst, const void* src) {
    asm volatile("cp.async.cg.shared.global [%0], [%1], 16;" :: "r"(dst), "l"(src));
}
#define CP_COMMIT() asm volatile("cp.async.commit_group;" ::: "memory")
#define CP_WAIT1()  asm volatile("cp.async.wait_group 1;" ::: "memory")

__device__ __forceinline__ void mma_f16(float* c, const uint32_t* a, const uint32_t* b) {
    asm volatile(
        "mma.sync.aligned.m16n8k16.row.col.f32.f16.f16.f32 "
        "{%0,%1,%2,%3}, {%4,%5,%6,%7}, {%8,%9}, {%0,%1,%2,%3};"
        : "+f"(c[0]), "+f"(c[1]), "+f"(c[2]), "+f"(c[3])
        : "r"(a[0]), "r"(a[1]), "r"(a[2]), "r"(a[3]), "r"(b[0]), "r"(b[1]));
}
__device__ __forceinline__ void ldsm_x4(uint32_t a, uint32_t* r) {
    asm volatile("ldmatrix.sync.aligned.m8n8.x4.shared.b16 {%0,%1,%2,%3}, [%4];"
                 : "=r"(r[0]), "=r"(r[1]), "=r"(r[2]), "=r"(r[3]) : "r"(a));
}

// ---------------------------------------------------------------------------
// Device scratch
// ---------------------------------------------------------------------------
__device__ __half g_qTh [16 * 1024 * 512];   // q^T fp16, [b][hw][c]
__device__ __half g_xTh [16 * 1024 * 512];   // x^T fp16, [b][hw][c]
__device__ __half g_xsh [16 * 256 * 512];    // sampled x fp16, [b][s][c]
__device__ __half g_kh  [16 * 512 * 256];    // k fp16, [bh][d][s]
__device__ __half g_vh  [16 * 512 * 256];    // v fp16
__device__ __half g_outTh[16 * 1024 * 512];  // attention out fp16, [b][m][c]
__device__ float  g_pos [16 * 4 * 256 * 2];
__device__ __half g_Wh  [4 * 512 * 512];     // Wq,Wk,Wv,Wo fp16

// ---------------------------------------------------------------------------
// Prep: x transpose + weight cvt, one launch.
// ---------------------------------------------------------------------------
__global__ __launch_bounds__(256)
void prep_kernel(const float* __restrict__ x, __half* __restrict__ xTh,
                 const float* __restrict__ Wq, const float* __restrict__ Wk,
                 const float* __restrict__ Wv, const float* __restrict__ Wo,
                 __half* __restrict__ Wh)
{
    if (blockIdx.x < 8192) {
        __shared__ float t[32][33];
        const int bid = blockIdx.x;
        const int b = bid >> 9;
        const int rem = bid & 511;
        const int hw0 = (rem & 31) * 32, c0 = (rem >> 5) * 32;
        const int tx = threadIdx.x & 31, ty = threadIdx.x >> 5;
        const float* xb = x + (size_t)b * 512 * 1024;
        __half* xTb = xTh + (size_t)b * 1024 * 512;
#pragma unroll
        for (int j = 0; j < 4; j++)
            t[ty + j * 8][tx] = xb[(size_t)(c0 + ty + j * 8) * 1024 + hw0 + tx];
        __syncthreads();
#pragma unroll
        for (int j = 0; j < 4; j++)
            xTb[(size_t)(hw0 + ty + j * 8) * 512 + c0 + tx] =
                __float2half(t[tx][ty + j * 8]);
    } else {
        const int cid = blockIdx.x - 8192;
        const int w = cid >> 10;
        const int i = (cid & 1023) * 256 + threadIdx.x;
        const float* src = (w == 0) ? Wq : (w == 1) ? Wk : (w == 2) ? Wv : Wo;
        Wh[(size_t)w * 262144 + i] = __float2half(src[i]);
    }
}

// ---------------------------------------------------------------------------
// cp.async-pipelined fp16 GEMM (k32 chunks, 3 stages, wait_group 1).
// 256 threads (8 warps 2m x 4n), tile 128x128.
// ---------------------------------------------------------------------------
#define HROW 80
#define HSTG_A (128 * HROW)
#define HSTG   (2 * HSTG_A)
#define GSM_BYTES (3 * HSTG)

template <int BIASN, int OUTH>
__device__ __forceinline__ void gemm_body(
    const __half* __restrict__ Am, const __half* __restrict__ Bm,
    const float* __restrict__ bias, void* __restrict__ Ybv,
    int N, int bm, int bn, char* sm)
{
    const int tid = threadIdx.x, lane = tid & 31, wid = tid >> 5;
    const int rg = lane >> 2, cl = lane & 3;
    const int wm = (wid >> 2) * 64, wn = (wid & 3) * 32;
    const uint32_t sb = smem_u32(sm);

    const int grp = lane >> 3, rr8 = lane & 7;
    const int arow = rr8 + (grp & 1) * 8;
    const uint32_t akb = (uint32_t)(grp >> 1) * 16;
    const int brow = (grp >> 1) * 8 + rr8;
    const uint32_t bkb = (uint32_t)(grp & 1) * 16;

    const int r = tid >> 1, hf = tid & 1;
    const __half* AgBase = Am + (size_t)(bm + r) * 512 + hf * 16;
    const __half* BgBase = Bm + (size_t)(bn + r) * 512 + hf * 16;
    const uint32_t doff = r * HROW + hf * 32;

    auto issue = [&](int stage, int k0) {
        uint32_t base = sb + stage * HSTG;
        cpasync16(base + doff,      AgBase + k0);
        cpasync16(base + doff + 16, AgBase + k0 + 8);
        uint32_t bb = base + HSTG_A;
        cpasync16(bb + doff,      BgBase + k0);
        cpasync16(bb + doff + 16, BgBase + k0 + 8);
        CP_COMMIT();
    };
    issue(0, 0);
    issue(1, 32);

    float acc[4][4][4];
#pragma unroll
    for (int i = 0; i < 4; i++)
#pragma unroll
        for (int j = 0; j < 4; j++)
#pragma unroll
            for (int rr = 0; rr < 4; rr++) acc[i][j][rr] = 0.f;

    for (int cidx = 0; cidx < 16; cidx++) {
        CP_WAIT1();
        __syncthreads();
        if (cidx + 2 < 16) issue((cidx + 2) % 3, (cidx + 2) * 32);
        else CP_COMMIT();

        const uint32_t sbase = sb + (cidx % 3) * HSTG;

#pragma unroll
        for (int ks = 0; ks < 2; ks++) {
            uint32_t af[4][4], bf[4][2];
#pragma unroll
            for (int i = 0; i < 4; i++)
                ldsm_x4(sbase + (wm + i * 16 + arow) * HROW + ks * 32 + akb, af[i]);
#pragma unroll
            for (int jp = 0; jp < 2; jp++) {
                uint32_t r4[4];
                ldsm_x4(sbase + HSTG_A + (wn + jp * 16 + brow) * HROW + ks * 32 + bkb, r4);
                bf[jp * 2][0] = r4[0]; bf[jp * 2][1] = r4[1];
                bf[jp * 2 + 1][0] = r4[2]; bf[jp * 2 + 1][1] = r4[3];
            }
#pragma unroll
            for (int i = 0; i < 4; i++)
#pragma unroll
                for (int j = 0; j < 4; j++)
                    mma_f16(acc[i][j], af[i], bf[j]);
        }
    }
    __syncthreads();

#pragma unroll
    for (int i = 0; i < 4; i++) {
        int m = bm + wm + i * 16 + rg;
        float b0 = 0.f, b1 = 0.f;
        if (!BIASN) { b0 = bias[m]; b1 = bias[m + 8]; }
#pragma unroll
        for (int j = 0; j < 4; j++) {
            float v00, v01, v10, v11;
            if (BIASN) {
                b0 = bias[bn + wn + 2 * cl + j * 8];
                b1 = bias[bn + wn + 2 * cl + j * 8 + 1];
                v00 = acc[i][j][0] + b0; v01 = acc[i][j][1] + b1;
                v10 = acc[i][j][2] + b0; v11 = acc[i][j][3] + b1;
            } else {
                v00 = acc[i][j][0] + b0; v01 = acc[i][j][1] + b0;
                v10 = acc[i][j][2] + b1; v11 = acc[i][j][3] + b1;
            }
            if (OUTH) {
                __half* Yb = (__half*)Ybv;
                __half* y0 = Yb + (size_t)m * N + bn + wn + 2 * cl + j * 8;
                __half* y1 = y0 + (size_t)8 * N;
                *(__half2*)y0 = __floats2half2_rn(v00, v01);
                *(__half2*)y1 = __floats2half2_rn(v10, v11);
            } else {
                float* Yb = (float*)Ybv;
                float* y0 = Yb + (size_t)m * N + bn + wn + 2 * cl + j * 8;
                float* y1 = y0 + (size_t)8 * N;
                *(float2*)y0 = make_float2(v00, v01);
                *(float2*)y1 = make_float2(v10, v11);
            }
        }
    }
}

__global__ __launch_bounds__(256, 2)
void gemm_mma(const __half* __restrict__ Wh, const __half* __restrict__ XT,
              const float* __restrict__ bias, float* __restrict__ Y, int N)
{
    extern __shared__ char gsm[];
    const int b = blockIdx.z;
    gemm_body<0, 0>(Wh, XT + (size_t)b * N * 512, bias, Y + (size_t)b * 512 * N,
                    N, blockIdx.y * 128, blockIdx.x * 128, gsm);
}

__global__ __launch_bounds__(256, 2)
void gemm_mma_q(const __half* __restrict__ WhQ, const __half* __restrict__ xTh,
                const float* __restrict__ bq, __half* __restrict__ qTh)
{
    extern __shared__ char gsm[];
    const int b = blockIdx.z;
    gemm_body<1, 1>(xTh + (size_t)b * 524288, WhQ, bq, qTh + (size_t)b * 524288,
                    512, blockIdx.y * 128, blockIdx.x * 128, gsm);
}

__global__ __launch_bounds__(256, 2)
void gemm_mma_kv(const __half* __restrict__ Wh, const float* __restrict__ bk,
                 const float* __restrict__ bv, const __half* __restrict__ XTh,
                 __half* __restrict__ Yk, __half* __restrict__ Yv)
{
    extern __shared__ char gsm[];
    const int b = blockIdx.z;
    const int isv = blockIdx.y >> 2;
    gemm_body<0, 1>(Wh + (size_t)(1 + isv) * 262144, XTh + (size_t)b * 256 * 512,
                    isv ? bv : bk, (isv ? Yv : Yk) + (size_t)b * 512 * 256,
                    256, (blockIdx.y & 3) * 128, blockIdx.x * 128, gsm);
}

// ---------------------------------------------------------------------------
// Offset network + FUSED bilinear sampling. 8192 blocks x 128 threads.
// Block = (bg, 2 positions). After pos is computed, the same block samples
// its group's 128 channels at both positions (1 half2 gather per thread).
// ---------------------------------------------------------------------------
__global__ __launch_bounds__(128)
void offset_sample_kernel(const float* __restrict__ dw_w, const float* __restrict__ dw_b,
                          const float* __restrict__ ln_g, const float* __restrict__ ln_b,
                          const float* __restrict__ pw_w,
                          float* __restrict__ out_pos, float* __restrict__ out_ref)
{
    __shared__ float ra[4], rb[4], rc[4], rd[4];
    __shared__ float spy[2], spx[2];

    const int blk = blockIdx.x;          // 8192
    const int n = blk >> 7;              // bg index 0..63
    const int sbase = (blk & 127) * 2;
    const int t = threadIdx.x;
    const int p = t >> 6;                // 0/1
    const int cp = t & 63;               // channel pair
    const int s = sbase + p;
    const int oy = s >> 4, ox = s & 15;
    const int bb = n >> 2, g = n & 3;
    const int lane = t & 31, warp = t >> 5;

    const __half2* qTb = (const __half2*)(g_qTh + (size_t)bb * 524288 + g * 128 + 2 * cp);

    float ax = dw_b[2 * cp], ay = dw_b[2 * cp + 1];
#pragma unroll
    for (int ky = 0; ky < 3; ky++) {
        int iy = oy * 2 - 1 + ky;
        if (iy < 0 || iy >= 32) continue;
#pragma unroll
        for (int kx = 0; kx < 3; kx++) {
            int ix = ox * 2 - 1 + kx;
            if (ix < 0 || ix >= 32) continue;
            float2 v = __half22float2(qTb[(size_t)(iy * 32 + ix) * 256]);
            ax += v.x * dw_w[(2 * cp) * 9 + ky * 3 + kx];
            ay += v.y * dw_w[(2 * cp + 1) * 9 + ky * 3 + kx];
        }
    }

    float s1 = ax + ay, s2 = ax * ax + ay * ay;
#pragma unroll
    for (int o = 16; o; o >>= 1) {
        s1 += __shfl_xor_sync(~0u, s1, o);
        s2 += __shfl_xor_sync(~0u, s2, o);
    }
    if (lane == 0) { ra[warp] = s1; rb[warp] = s2; }
    __syncthreads();
    float sum = ra[p * 2] + ra[p * 2 + 1];
    float sumsq = rb[p * 2] + rb[p * 2 + 1];
    float mean = sum * (1.f / 128.f);
    float var = sumsq * (1.f / 128.f) - mean * mean;
    float inv = rsqrtf(var + 1e-5f);
    float ox0 = (ax - mean) * inv * ln_g[2 * cp] + ln_b[2 * cp];
    float ox1 = (ay - mean) * inv * ln_g[2 * cp + 1] + ln_b[2 * cp + 1];
    ox0 = 0.5f * ox0 * (1.f + erff(ox0 * 0.70710678118654752f));
    ox1 = 0.5f * ox1 * (1.f + erff(ox1 * 0.70710678118654752f));

    float d0 = ox0 * pw_w[2 * cp] + ox1 * pw_w[2 * cp + 1];
    float d1 = ox0 * pw_w[128 + 2 * cp] + ox1 * pw_w[128 + 2 * cp + 1];
#pragma unroll
    for (int o = 16; o; o >>= 1) {
        d0 += __shfl_xor_sync(~0u, d0, o);
        d1 += __shfl_xor_sync(~0u, d1, o);
    }
    if (lane == 0) { rc[warp] = d0; rd[warp] = d1; }
    __syncthreads();

    if (cp == 0) {
        float vy = rc[p * 2] + rc[p * 2 + 1];
        float vx = rd[p * 2] + rd[p * 2 + 1];
        float offy = tanhf(vy) * (2.f / 15.f);
        float offx = tanhf(vx) * (2.f / 15.f);
        float refy = (0.5f + (float)oy) * (2.f / 15.f) - 1.f;
        float refx = (0.5f + (float)ox) * (2.f / 15.f) - 1.f;
        float py = offy + refy, px = offx + refx;
        int idx = (n * 256 + s) * 2;
        g_pos[idx] = py;  g_pos[idx + 1] = px;
        out_pos[idx] = py; out_pos[idx + 1] = px;
        out_ref[idx] = refy; out_ref[idx + 1] = refx;
        spy[p] = py; spx[p] = px;
    }
    __syncthreads();

    // ---- fused bilinear sampling: channels [g*128,(g+1)*128) at position s ----
    {
        float py = spy[p], px = spx[p];
        float gx = (px + 1.f) * 15.5f;
        float gy = (py + 1.f) * 15.5f;

        const __half2* xb = (const __half2*)(g_xTh + (size_t)bb * 524288) + g * 64 + cp;

        float fx0 = floorf(gx), fy0 = floorf(gy);
        int x0 = (int)fx0, y0 = (int)fy0;
        float wx1 = gx - fx0, wx0 = 1.f - wx1;
        float wy1 = gy - fy0, wy0 = 1.f - wy1;

        bool x0i = (x0 >= 0 && x0 < 32), x1i = (x0 >= -1 && x0 < 31);
        bool y0i = (y0 >= 0 && y0 < 32), y1i = (y0 >= -1 && y0 < 31);

        float2 z = make_float2(0.f, 0.f);
        float2 v00 = (y0i && x0i) ? __half22float2(xb[(size_t)(y0 * 32 + x0) * 256])           : z;
        float2 v01 = (y0i && x1i) ? __half22float2(xb[(size_t)(y0 * 32 + x0 + 1) * 256])       : z;
        float2 v10 = (y1i && x0i) ? __half22float2(xb[(size_t)((y0 + 1) * 32 + x0) * 256])     : z;
        float2 v11 = (y1i && x1i) ? __half22float2(xb[(size_t)((y0 + 1) * 32 + x0 + 1) * 256]) : z;

        float rx = wy0 * (wx0 * v00.x + wx1 * v01.x) + wy1 * (wx0 * v10.x + wx1 * v11.x);
        float ry = wy0 * (wx0 * v00.y + wx1 * v01.y) + wy1 * (wx0 * v10.y + wx1 * v11.y);
        ((__half2*)(g_xsh + (size_t)bb * 131072 + s * 512))[g * 64 + cp] =
            __floats2half2_rn(rx, ry);
    }
}

// ---------------------------------------------------------------------------
// Fused attention. Scale folded into K staging; plain half2 Q copy.
// 128 blocks, 512 threads (16 warps 4m x 4n), 128-query tiles.
// ---------------------------------------------------------------------------
#define KT_OFF 0
#define VT_OFF 36864
#define PQ_OFF 70656
#define F32_OFF 138240
#define ATTN_SMEM_BYTES (F32_OFF + 6020 * 4)

__global__ __launch_bounds__(512, 1)
void attn_mma(const float* __restrict__ rpe)
{
    extern __shared__ char smc[];
    __half* Kt  = (__half*)(smc + KT_OFF);
    __half* Vt  = (__half*)(smc + VT_OFF);
    __half* PQh = (__half*)(smc + PQ_OFF);
    float* tab   = (float*)(smc + F32_OFF);
    int*   xbase = (int*)(tab + 3972);
    float* wxf0  = (float*)(xbase + 256);
    float* wxf1  = wxf0 + 256;
    int*   ybase = (int*)(wxf1 + 256);
    float* wyf0  = (float*)(ybase + 256);
    float* wyf1  = wyf0 + 256;
    float* redS  = wyf1 + 256;

    const int bh = blockIdx.x;
    const int b = bh >> 3, h8 = bh & 7;
    const int g = h8 >> 1;
    const int tid = threadIdx.x;
    const int lane = tid & 31, wid = tid >> 5;
    const int rg = lane >> 2, c = lane & 3;
    const int wmw = (wid & 3) * 32;
    const int wn4 = wid >> 2;
    const int wn  = wn4 * 64;
    const int wd  = wn4 * 16;
    const int selw = wid & 3;
    const uint32_t sb = smem_u32(smc);

    const int grp = lane >> 3, rr8 = lane & 7;
    const int arow = rr8 + (grp & 1) * 8;
    const uint32_t akb = (uint32_t)(grp >> 1) * 16;
    const int brow = (grp >> 1) * 8 + rr8;
    const uint32_t bkb = (uint32_t)(grp & 1) * 16;

    const __half* kg = g_kh + (size_t)bh * 16384;
    const __half* vg = g_vh + (size_t)bh * 16384;
    const __half hs = __float2half(0.125f);
    for (int i = tid; i < 16384; i += 512) {
        int d = i >> 8, s = i & 255;
        Kt[s * 72 + d]  = __hmul(kg[i], hs);
        Vt[d * 264 + s] = vg[i];
    }
    for (int i = tid; i < 3969; i += 512) tab[i] = rpe[h8 * 3969 + i];
    if (tid < 256) {
        int pidx = ((b * 4 + g) * 256 + tid) * 2;
        float by = 15.5f - 15.5f * g_pos[pidx];
        float bx = 15.5f - 15.5f * g_pos[pidx + 1];
        float fby = floorf(by), fbx = floorf(bx);
        ybase[tid] = (int)fby;
        wyf1[tid] = by - fby;
        wyf0[tid] = 1.f - (by - fby);
        xbase[tid] = (int)fbx;
        wxf1[tid] = bx - fbx;
        wxf0[tid] = 1.f - (bx - fbx);
    }
    __syncthreads();

    const __half* qgTh = g_qTh + (size_t)b * 524288 + h8 * 64;
    __half* outg = g_outTh + (size_t)b * 524288 + h8 * 64;

    int mxi[2][2];
#pragma unroll
    for (int i = 0; i < 2; i++)
#pragma unroll
        for (int r2 = 0; r2 < 2; r2++)
            mxi[i][r2] = (wmw + i * 16 + rg + r2 * 8) & 31;

    for (int m0 = 0; m0 < 1024; m0 += 128) {
        for (int i = tid; i < 4096; i += 512) {
            int m = i >> 5, d2 = (i & 31) * 2;
            *(__half2*)(PQh + m * 72 + d2) =
                *(const __half2*)(qgTh + (size_t)(m0 + m) * 512 + d2);
        }
        __syncthreads();

        const int myt = (m0 >> 5) + selw;

        float sacc[2][8][4];
#pragma unroll
        for (int i = 0; i < 2; i++)
#pragma unroll
            for (int t = 0; t < 8; t++)
#pragma unroll
                for (int r = 0; r < 4; r++) sacc[i][t][r] = 0.f;

#pragma unroll
        for (int ks = 0; ks < 4; ks++) {
            uint32_t af[2][4], bf[8][2];
#pragma unroll
            for (int i = 0; i < 2; i++)
                ldsm_x4(sb + PQ_OFF + (wmw + i * 16 + arow) * 144 + ks * 32 + akb, af[i]);
#pragma unroll
            for (int tp = 0; tp < 4; tp++) {
                uint32_t r4[4];
                ldsm_x4(sb + KT_OFF + (wn + tp * 16 + brow) * 144 + ks * 32 + bkb, r4);
                bf[tp * 2][0] = r4[0]; bf[tp * 2][1] = r4[1];
                bf[tp * 2 + 1][0] = r4[2]; bf[tp * 2 + 1][1] = r4[3];
            }
#pragma unroll
            for (int t = 0; t < 8; t++) {
                mma_f16(sacc[0][t], af[0], bf[t]);
                mma_f16(sacc[1][t], af[1], bf[t]);
            }
        }

#pragma unroll
        for (int t = 0; t < 8; t++) {
#pragma unroll
            for (int cc = 0; cc < 2; cc++) {
                int n = wn + t * 8 + 2 * c + cc;
                int y0 = myt + ybase[n];
                float w0 = (y0 >= 0 && y0 < 63) ? wyf0[n] : 0.f;
                float w1 = (y0 >= -1 && y0 < 62) ? wyf1[n] : 0.f;
                int o0 = min(max(y0, 0), 62) * 63;
                int o1 = min(max(y0 + 1, 0), 62) * 63;
                int xb = xbase[n];
                float wx0n = wxf0[n], wx1n = wxf1[n];
#pragma unroll
                for (int i = 0; i < 2; i++) {
#pragma unroll
                    for (int r2 = 0; r2 < 2; r2++) {
                        int x0 = mxi[i][r2] + xb;
                        float u0 = (x0 >= 0 && x0 < 63) ? wx0n : 0.f;
                        float u1 = (x0 >= -1 && x0 < 62) ? wx1n : 0.f;
                        int x0c = min(max(x0, 0), 62);
                        int x1c = min(max(x0 + 1, 0), 62);
                        float bias = w0 * (u0 * tab[o0 + x0c] + u1 * tab[o0 + x1c])
                                   + w1 * (u0 * tab[o1 + x0c] + u1 * tab[o1 + x1c]);
                        sacc[i][t][r2 * 2 + cc] += bias;
                    }
                }
            }
        }
        __syncthreads();

#pragma unroll
        for (int i = 0; i < 2; i++) {
#pragma unroll
            for (int r2 = 0; r2 < 2; r2++) {
                int m_l = wmw + i * 16 + rg + r2 * 8;
                float sum = 0.f;
#pragma unroll
                for (int t = 0; t < 8; t++) {
                    float e0 = __expf(sacc[i][t][r2 * 2 + 0]);
                    float e1 = __expf(sacc[i][t][r2 * 2 + 1]);
                    sum += e0 + e1;
                    *(__half2*)(smc + PQ_OFF + m_l * 528 + (wn + t * 8 + 2 * c) * 2) =
                        __floats2half2_rn(e0, e1);
                }
                sum += __shfl_xor_sync(~0u, sum, 1);
                sum += __shfl_xor_sync(~0u, sum, 2);
                if (c == 0) redS[m_l * 4 + wn4] = sum;
            }
        }
        __syncthreads();

        float oacc[2][2][4];
#pragma unroll
        for (int i = 0; i < 2; i++)
#pragma unroll
            for (int j = 0; j < 2; j++)
#pragma unroll
                for (int r = 0; r < 4; r++) oacc[i][j][r] = 0.f;

#pragma unroll 4
        for (int ks = 0; ks < 16; ks++) {
            uint32_t af[2][4], bf[2][2];
#pragma unroll
            for (int i = 0; i < 2; i++)
                ldsm_x4(sb + PQ_OFF + (wmw + i * 16 + arow) * 528 + ks * 32 + akb, af[i]);
            {
                uint32_t r4[4];
                ldsm_x4(sb + VT_OFF + (wd + brow) * 528 + ks * 32 + bkb, r4);
                bf[0][0] = r4[0]; bf[0][1] = r4[1];
                bf[1][0] = r4[2]; bf[1][1] = r4[3];
            }
#pragma unroll
            for (int j = 0; j < 2; j++) {
                mma_f16(oacc[0][j], af[0], bf[j]);
                mma_f16(oacc[1][j], af[1], bf[j]);
            }
        }

#pragma unroll
        for (int i = 0; i < 2; i++) {
#pragma unroll
            for (int r2 = 0; r2 < 2; r2++) {
                int m_l = wmw + i * 16 + rg + r2 * 8;
                const float* rs = redS + m_l * 4;
                float inv = 1.f / (rs[0] + rs[1] + rs[2] + rs[3]);
                __half* orow = outg + (size_t)(m0 + m_l) * 512;
#pragma unroll
                for (int j = 0; j < 2; j++) {
                    float o0 = oacc[i][j][r2 * 2 + 0] * inv;
                    float o1 = oacc[i][j][r2 * 2 + 1] * inv;
                    *(__half2*)(orow + wd + j * 8 + 2 * c) = __floats2half2_rn(o0, o1);
                }
            }
        }
        __syncthreads();
    }
}

// ---------------------------------------------------------------------------
// Launch
// ---------------------------------------------------------------------------
extern "C" void kernel_launch(void* const* d_in, const int* in_sizes, int n_in,
                              void* d_out, int out_size)
{
    const float* x    = (const float*)d_in[0];
    const float* Wq   = (const float*)d_in[1];
    const float* bq   = (const float*)d_in[2];
    const float* Wk   = (const float*)d_in[3];
    const float* bk   = (const float*)d_in[4];
    const float* Wv   = (const float*)d_in[5];
    const float* bv   = (const float*)d_in[6];
    const float* Wo   = (const float*)d_in[7];
    const float* bo   = (const float*)d_in[8];
    const float* dw_w = (const float*)d_in[9];
    const float* dw_b = (const float*)d_in[10];
    const float* ln_g = (const float*)d_in[11];
    const float* ln_b = (const float*)d_in[12];
    const float* pw_w = (const float*)d_in[13];
    const float* rpe  = (const float*)d_in[14];

    float* out     = (float*)d_out;
    float* y_out   = out;
    float* pos_out = out + 8388608;
    float* ref_out = out + 8388608 + 32768;

    void *p_qTh, *p_xTh, *p_xsh, *p_kh, *p_vh, *p_outTh, *p_Wh;
    cudaGetSymbolAddress(&p_qTh,   g_qTh);
    cudaGetSymbolAddress(&p_xTh,   g_xTh);
    cudaGetSymbolAddress(&p_xsh,   g_xsh);
    cudaGetSymbolAddress(&p_kh,    g_kh);
    cudaGetSymbolAddress(&p_vh,    g_vh);
    cudaGetSymbolAddress(&p_outTh, g_outTh);
    cudaGetSymbolAddress(&p_Wh,    g_Wh);

    cudaFuncSetAttribute(gemm_mma,    cudaFuncAttributeMaxDynamicSharedMemorySize, GSM_BYTES);
    cudaFuncSetAttribute(gemm_mma_q,  cudaFuncAttributeMaxDynamicSharedMemorySize, GSM_BYTES);
    cudaFuncSetAttribute(gemm_mma_kv, cudaFuncAttributeMaxDynamicSharedMemorySize, GSM_BYTES);
    cudaFuncSetAttribute(attn_mma,    cudaFuncAttributeMaxDynamicSharedMemorySize, ATTN_SMEM_BYTES);

    const __half* Wh = (const __half*)p_Wh;

    prep_kernel<<<12288, 256>>>(x, (__half*)p_xTh, Wq, Wk, Wv, Wo, (__half*)p_Wh);
    gemm_mma_q<<<dim3(4, 8, 16), 256, GSM_BYTES>>>(Wh, (const __half*)p_xTh, bq,
                                                   (__half*)p_qTh);
    // offset network + fused bilinear sampling -> pos, ref, xs
    offset_sample_kernel<<<8192, 128>>>(dw_w, dw_b, ln_g, ln_b, pw_w, pos_out, ref_out);
    gemm_mma_kv<<<dim3(2, 8, 16), 256, GSM_BYTES>>>(Wh, bk, bv, (const __half*)p_xsh,
                                                    (__half*)p_kh, (__half*)p_vh);
    attn_mma<<<128, 512, ATTN_SMEM_BYTES>>>(rpe);
    gemm_mma<<<dim3(8, 4, 16), 256, GSM_BYTES>>>(Wh + 3 * 262144, (const __half*)p_outTh,
                                                 bo, y_out, 1024);
}